// round 10
// baseline (speedup 1.0000x reference)
#include <cuda_runtime.h>
#include <cuda_bf16.h>
#include <cstdint>

#define BB 2
#define SS 2048
#define DD 1024
#define HH 16
#define DKH 64
#define BHH (BB*HH)

// ---------------------------------------------------------------------------
// Scratch (allocation-free rule: __device__ globals) — all bf16 hi/lo pairs
// ---------------------------------------------------------------------------
__device__ __nv_bfloat16 g_xhi[BB * SS * DD];
__device__ __nv_bfloat16 g_xlo[BB * SS * DD];
__device__ __nv_bfloat16 g_whi[3 * HH * DKH * DD];   // [(proj*16+h)*64+n][k]
__device__ __nv_bfloat16 g_wlo[3 * HH * DKH * DD];
__device__ __nv_bfloat16 g_qhi[BHH * SS * DKH];      // [bh][s][64] (x 1/8)
__device__ __nv_bfloat16 g_qlo[BHH * SS * DKH];
__device__ __nv_bfloat16 g_khi[BHH * SS * DKH];
__device__ __nv_bfloat16 g_klo[BHH * SS * DKH];
__device__ __nv_bfloat16 g_vhi[BHH * SS * DKH];
__device__ __nv_bfloat16 g_vlo[BHH * SS * DKH];
__device__ __nv_bfloat16 g_chi[BB * SS * HH * DKH];  // ctx [token][1024]
__device__ __nv_bfloat16 g_clo[BB * SS * HH * DKH];
__device__ __nv_bfloat16 g_wohi[DD * DD];            // Wo^T [n][k]
__device__ __nv_bfloat16 g_wolo[DD * DD];

// ---------------------------------------------------------------------------
// Helpers
// ---------------------------------------------------------------------------
__device__ __forceinline__ uint32_t smem_to_u32(const void* p) {
    uint32_t a;
    asm("{ .reg .u64 t; cvta.to.shared.u64 t, %1; cvt.u32.u64 %0, t; }"
        : "=r"(a) : "l"(p));
    return a;
}
__device__ __forceinline__ void ldsm_x4(uint32_t addr, uint32_t* r) {
    asm volatile("ldmatrix.sync.aligned.m8n8.x4.shared.b16 {%0,%1,%2,%3}, [%4];"
        : "=r"(r[0]), "=r"(r[1]), "=r"(r[2]), "=r"(r[3]) : "r"(addr));
}
__device__ __forceinline__ void ldsm_x4_t(uint32_t addr, uint32_t* r) {
    asm volatile("ldmatrix.sync.aligned.m8n8.x4.trans.shared.b16 {%0,%1,%2,%3}, [%4];"
        : "=r"(r[0]), "=r"(r[1]), "=r"(r[2]), "=r"(r[3]) : "r"(addr));
}
__device__ __forceinline__ void mma_bf16(float* d, const uint32_t* a,
                                         uint32_t b0, uint32_t b1) {
    asm volatile(
        "mma.sync.aligned.m16n8k16.row.col.f32.bf16.bf16.f32 "
        "{%0,%1,%2,%3}, {%4,%5,%6,%7}, {%8,%9}, {%0,%1,%2,%3};"
        : "+f"(d[0]), "+f"(d[1]), "+f"(d[2]), "+f"(d[3])
        : "r"(a[0]), "r"(a[1]), "r"(a[2]), "r"(a[3]), "r"(b0), "r"(b1));
}
__device__ __forceinline__ uint32_t pkbf(float lo, float hi) {
    uint32_t r;
    asm("cvt.rn.bf16x2.f32 %0, %1, %2;" : "=r"(r) : "f"(hi), "f"(lo));
    return r;
}
__device__ __forceinline__ void split2(float v, __nv_bfloat16& h, float& l) {
    h = __float2bfloat16(v);
    l = v - __bfloat162float(h);
}
__device__ __forceinline__ void cpasync16(uint32_t dst, const void* src) {
    asm volatile("cp.async.cg.shared.global [%0], [%1], 16;"
                 :: "r"(dst), "l"(src));
}
#define CP_COMMIT() asm volatile("cp.async.commit_group;" ::: "memory")
#define CP_WAIT1()  asm volatile("cp.async.wait_group 1;" ::: "memory")
#define CP_WAIT0()  asm volatile("cp.async.wait_group 0;" ::: "memory")

// ---------------------------------------------------------------------------
// Prep A: split X into bf16 hi/lo.
// ---------------------------------------------------------------------------
__global__ __launch_bounds__(256) void conv_x_kernel(const float4* __restrict__ X4)
{
    int i0 = blockIdx.x * 256 + threadIdx.x;
    #pragma unroll
    for (int l = 0; l < 2; l++) {
        int i = i0 + l * 524288;
        float4 v = X4[i];
        float vv[4] = {v.x, v.y, v.z, v.w};
        union { float2 f; __nv_bfloat16 h[4]; } hi, lo;
        #pragma unroll
        for (int j = 0; j < 4; j++) {
            float lw; split2(vv[j], hi.h[j], lw);
            lo.h[j] = __float2bfloat16(lw);
        }
        ((float2*)g_xhi)[i] = hi.f;
        ((float2*)g_xlo)[i] = lo.f;
    }
}

// ---------------------------------------------------------------------------
// Prep B: transpose + split Wq/Wk/Wv.
// ---------------------------------------------------------------------------
__global__ __launch_bounds__(256) void conv_w_kernel(
    const float* __restrict__ Wq, const float* __restrict__ Wk,
    const float* __restrict__ Wv)
{
    __shared__ float ts[64][65];
    const int k0   = blockIdx.x * 64;
    const int h    = blockIdx.y;
    const int proj = blockIdx.z;
    const float* W = (proj == 0) ? Wq : (proj == 1) ? Wk : Wv;
    W += (size_t)h * DD * DKH;

    const int tid = threadIdx.x;
    #pragma unroll
    for (int l = 0; l < 4; l++) {
        int idx = tid + l * 256;
        int r = idx >> 4, c4 = idx & 15;
        float4 v = *(const float4*)&W[(size_t)(k0 + r) * DKH + c4 * 4];
        ts[r][c4 * 4 + 0] = v.x;
        ts[r][c4 * 4 + 1] = v.y;
        ts[r][c4 * 4 + 2] = v.z;
        ts[r][c4 * 4 + 3] = v.w;
    }
    __syncthreads();
    #pragma unroll
    for (int l = 0; l < 4; l++) {
        int idx = tid + l * 256;
        int nr = idx >> 4, kc = idx & 15;
        size_t orow = ((size_t)(proj * HH + h) * DKH + nr) * DD + k0 + kc * 4;
        #pragma unroll
        for (int j = 0; j < 4; j++) {
            float v = ts[kc * 4 + j][nr];
            __nv_bfloat16 hb; float lw; split2(v, hb, lw);
            g_whi[orow + j] = hb;
            g_wlo[orow + j] = __float2bfloat16(lw);
        }
    }
}

// ---------------------------------------------------------------------------
// Prep C: transpose + split Wo.
// ---------------------------------------------------------------------------
__global__ __launch_bounds__(256) void conv_wo_kernel(const float* __restrict__ Wo)
{
    __shared__ float ts[64][65];
    const int k0 = blockIdx.x * 64;
    const int n0 = blockIdx.y * 64;
    const int tid = threadIdx.x;
    #pragma unroll
    for (int l = 0; l < 4; l++) {
        int idx = tid + l * 256;
        int r = idx >> 4, c4 = idx & 15;
        float4 v = *(const float4*)&Wo[(size_t)(k0 + r) * DD + n0 + c4 * 4];
        ts[r][c4 * 4 + 0] = v.x;
        ts[r][c4 * 4 + 1] = v.y;
        ts[r][c4 * 4 + 2] = v.z;
        ts[r][c4 * 4 + 3] = v.w;
    }
    __syncthreads();
    #pragma unroll
    for (int l = 0; l < 4; l++) {
        int idx = tid + l * 256;
        int nr = idx >> 4, kc = idx & 15;
        size_t orow = (size_t)(n0 + nr) * DD + k0 + kc * 4;
        #pragma unroll
        for (int j = 0; j < 4; j++) {
            float v = ts[kc * 4 + j][nr];
            __nv_bfloat16 hb; float lw; split2(v, hb, lw);
            g_wohi[orow + j] = hb;
            g_wolo[orow + j] = __float2bfloat16(lw);
        }
    }
}

// ---------------------------------------------------------------------------
// Pipelined GEMM plumbing: M128 x N128 CTA, K chunks of 32, 2 stages.
// Warp tile 64x32 (2M x 4N warps). Pass-major MMA ordering (same-acc
// distance = 16 instructions; asm volatile preserves source order).
// ---------------------------------------------------------------------------
#define CROWB 80
#define CTILE (128 * CROWB)       // 10240
#define CSTAGE (4 * CTILE)        // 40960 : AHI | ALO | BHI | BLO
#define GSM_BYTES (2 * CSTAGE)    // 81920

__device__ __forceinline__ void load_stage_g(
    uint32_t sm,
    const __nv_bfloat16* __restrict__ Ahi, const __nv_bfloat16* __restrict__ Alo,
    const __nv_bfloat16* __restrict__ Bhi, const __nv_bfloat16* __restrict__ Blo,
    int k0, int tid)
{
    #pragma unroll
    for (int l = 0; l < 2; l++) {
        int idx = tid + l * 256;
        int r = idx >> 2, c = idx & 3;
        uint32_t dof = (uint32_t)(r * CROWB + c * 16);
        size_t   sof = ((size_t)r * DD + k0) * 2 + c * 16;
        cpasync16(sm + 0 * CTILE + dof, (const char*)Ahi + sof);
        cpasync16(sm + 1 * CTILE + dof, (const char*)Alo + sof);
        cpasync16(sm + 2 * CTILE + dof, (const char*)Bhi + sof);
        cpasync16(sm + 3 * CTILE + dof, (const char*)Blo + sof);
    }
}

__device__ __forceinline__ void gemm_body(
    uint32_t smem_base, uint32_t a_lane, uint32_t b_lane,
    const __nv_bfloat16* Ahi, const __nv_bfloat16* Alo,
    const __nv_bfloat16* Bhi, const __nv_bfloat16* Blo,
    int tid, float acc[4][4][4])
{
    load_stage_g(smem_base, Ahi, Alo, Bhi, Blo, 0, tid);
    CP_COMMIT();
    load_stage_g(smem_base + CSTAGE, Ahi, Alo, Bhi, Blo, 32, tid);
    CP_COMMIT();

    for (int ch = 0; ch < 32; ch++) {
        if (ch >= 30) { CP_WAIT0(); } else { CP_WAIT1(); }
        __syncthreads();
        const uint32_t st = smem_base + (uint32_t)(ch & 1) * CSTAGE;

        #pragma unroll
        for (int ks = 0; ks < 2; ks++) {
            const uint32_t koff = ks * 32;
            uint32_t ahi[4][4], alo[4][4];
            #pragma unroll
            for (int am = 0; am < 4; am++) {
                ldsm_x4(st + 0 * CTILE + a_lane + am * 16 * CROWB + koff, ahi[am]);
                ldsm_x4(st + 1 * CTILE + a_lane + am * 16 * CROWB + koff, alo[am]);
            }
            uint32_t bhi[2][4], blo[2][4];
            #pragma unroll
            for (int bn = 0; bn < 2; bn++) {
                ldsm_x4(st + 2 * CTILE + b_lane + bn * 16 * CROWB + koff, bhi[bn]);
                ldsm_x4(st + 3 * CTILE + b_lane + bn * 16 * CROWB + koff, blo[bn]);
            }
            // pass 1: ahi x bhi  (16 independent MMAs)
            #pragma unroll
            for (int am = 0; am < 4; am++)
                #pragma unroll
                for (int bn = 0; bn < 2; bn++) {
                    mma_bf16(acc[am][2*bn],   ahi[am], bhi[bn][0], bhi[bn][2]);
                    mma_bf16(acc[am][2*bn+1], ahi[am], bhi[bn][1], bhi[bn][3]);
                }
            // pass 2: ahi x blo
            #pragma unroll
            for (int am = 0; am < 4; am++)
                #pragma unroll
                for (int bn = 0; bn < 2; bn++) {
                    mma_bf16(acc[am][2*bn],   ahi[am], blo[bn][0], blo[bn][2]);
                    mma_bf16(acc[am][2*bn+1], ahi[am], blo[bn][1], blo[bn][3]);
                }
            // pass 3: alo x bhi
            #pragma unroll
            for (int am = 0; am < 4; am++)
                #pragma unroll
                for (int bn = 0; bn < 2; bn++) {
                    mma_bf16(acc[am][2*bn],   alo[am], bhi[bn][0], bhi[bn][2]);
                    mma_bf16(acc[am][2*bn+1], alo[am], bhi[bn][1], bhi[bn][3]);
                }
        }
        __syncthreads();
        if (ch + 2 < 32) {
            load_stage_g(smem_base + (uint32_t)(ch & 1) * CSTAGE,
                         Ahi, Alo, Bhi, Blo, (ch + 2) * 32, tid);
            CP_COMMIT();
        }
    }
}

// ---------------------------------------------------------------------------
// QKV GEMM: writes Q/K/V as bf16 hi/lo (Q scaled by 1/8).
// ---------------------------------------------------------------------------
__global__ __launch_bounds__(256) void qkv_mma_kernel(
    const float* __restrict__ bq, const float* __restrict__ bk,
    const float* __restrict__ bv)
{
    extern __shared__ char smem[];
    const uint32_t smem_base = smem_to_u32(smem);
    const int tid  = threadIdx.x;
    const int lane = tid & 31;
    const int wid  = tid >> 5;
    const int warpM = wid & 1;          // 2 groups x 64 rows
    const int warpN = wid >> 1;         // 4 groups x 32 cols

    const int m0   = blockIdx.x * 128;
    const int hg   = blockIdx.y;
    const int proj = blockIdx.z;

    const float* bias = (proj == 0) ? bq : (proj == 1) ? bk : bv;
    __nv_bfloat16* ohi = (proj == 0) ? g_qhi : (proj == 1) ? g_khi : g_vhi;
    __nv_bfloat16* olo = (proj == 0) ? g_qlo : (proj == 1) ? g_klo : g_vlo;
    const float scale = (proj == 0) ? 0.125f : 1.0f;

    const size_t brow = ((size_t)proj * HH * DKH + (size_t)hg * 128) * DD;

    float acc[4][4][4] = {};

    const int lrow  = lane & 15;
    const int lhalf = lane >> 4;
    const uint32_t a_lane = (uint32_t)((warpM * 64 + lrow) * CROWB + lhalf * 16);
    const uint32_t b_lane = (uint32_t)((warpN * 32 + lrow) * CROWB + lhalf * 16);

    gemm_body(smem_base, a_lane, b_lane,
              g_xhi + (size_t)m0 * DD, g_xlo + (size_t)m0 * DD,
              g_whi + brow, g_wlo + brow, tid, acc);

    #pragma unroll
    for (int am = 0; am < 4; am++) {
        #pragma unroll
        for (int rh = 0; rh < 2; rh++) {
            const int token = m0 + warpM * 64 + am * 16 + rh * 8 + (lane >> 2);
            const int b_ = token >> 11;
            const int s_ = token & (SS - 1);
            #pragma unroll
            for (int na = 0; na < 4; na++) {
                const int ng = hg * 128 + warpN * 32 + na * 8 + (lane & 3) * 2;
                const int h  = ng >> 6;
                const int dk = ng & 63;
                float v0 = (acc[am][na][rh*2+0] + __ldg(&bias[h*DKH + dk]))   * scale;
                float v1 = (acc[am][na][rh*2+1] + __ldg(&bias[h*DKH + dk+1])) * scale;
                __nv_bfloat16 h0, h1; float l0, l1;
                split2(v0, h0, l0); split2(v1, h1, l1);
                size_t idx = ((size_t)(b_ * HH + h) * SS + s_) * DKH + dk;
                *(__nv_bfloat162*)&ohi[idx] = __nv_bfloat162(h0, h1);
                *(__nv_bfloat162*)&olo[idx] =
                    __nv_bfloat162(__float2bfloat16(l0), __float2bfloat16(l1));
            }
        }
    }
}

// ---------------------------------------------------------------------------
// Output projection: out = ctx @ Wo + bo (fp32 out).
// ---------------------------------------------------------------------------
__global__ __launch_bounds__(256) void out_mma_kernel(
    const float* __restrict__ bo, float* __restrict__ out)
{
    extern __shared__ char smem[];
    const uint32_t smem_base = smem_to_u32(smem);
    const int tid  = threadIdx.x;
    const int lane = tid & 31;
    const int wid  = tid >> 5;
    const int warpM = wid & 1;
    const int warpN = wid >> 1;

    const int m0 = blockIdx.x * 128;
    const int n0 = blockIdx.y * 128;

    float acc[4][4][4] = {};

    const int lrow  = lane & 15;
    const int lhalf = lane >> 4;
    const uint32_t a_lane = (uint32_t)((warpM * 64 + lrow) * CROWB + lhalf * 16);
    const uint32_t b_lane = (uint32_t)((warpN * 32 + lrow) * CROWB + lhalf * 16);

    gemm_body(smem_base, a_lane, b_lane,
              g_chi + (size_t)m0 * DD, g_clo + (size_t)m0 * DD,
              g_wohi + (size_t)n0 * DD, g_wolo + (size_t)n0 * DD, tid, acc);

    #pragma unroll
    for (int am = 0; am < 4; am++) {
        #pragma unroll
        for (int rh = 0; rh < 2; rh++) {
            const int token = m0 + warpM * 64 + am * 16 + rh * 8 + (lane >> 2);
            #pragma unroll
            for (int na = 0; na < 4; na++) {
                const int n = n0 + warpN * 32 + na * 8 + (lane & 3) * 2;
                float2 o;
                o.x = acc[am][na][rh*2+0] + __ldg(&bo[n]);
                o.y = acc[am][na][rh*2+1] + __ldg(&bo[n+1]);
                *(float2*)&out[(size_t)token * DD + n] = o;
            }
        }
    }
}

// ---------------------------------------------------------------------------
// Flash attention, pipelined, 32 q-rows per warp (q-tile 256).
// grid (8 q-tiles, 32 bh); block 256. Pass-major MMA ordering in S and PV.
// ---------------------------------------------------------------------------
#define AROWB 144                    // 72 bf16 per row
#define ATILE (64 * AROWB)           // 9216
#define AST (4 * ATILE)              // 36864 : KHI | KLO | VHI | VLO
#define ATTN_SM_BYTES (2 * AST)      // 73728

__device__ __forceinline__ void attn_load_stage(
    uint32_t sm, size_t key0, int tid)
{
    #pragma unroll
    for (int l = 0; l < 2; l++) {
        int idx = tid + l * 256;
        int r = idx >> 3, c = idx & 7;
        uint32_t dof = (uint32_t)(r * AROWB + c * 16);
        size_t   sof = ((size_t)r * DKH) * 2 + c * 16;
        cpasync16(sm + 0 * ATILE + dof, (const char*)(g_khi + key0) + sof);
        cpasync16(sm + 1 * ATILE + dof, (const char*)(g_klo + key0) + sof);
        cpasync16(sm + 2 * ATILE + dof, (const char*)(g_vhi + key0) + sof);
        cpasync16(sm + 3 * ATILE + dof, (const char*)(g_vlo + key0) + sof);
    }
}

__global__ __launch_bounds__(256, 1) void attn_mma_kernel()
{
    extern __shared__ char smem[];
    const uint32_t smem_base = smem_to_u32(smem);
    const int tid  = threadIdx.x;
    const int lane = tid & 31;
    const int w    = tid >> 5;          // warp 0..7 -> q rows w*32..w*32+31

    const int bh = blockIdx.y;
    const int q0 = blockIdx.x * 256;
    const size_t base = (size_t)bh * SS * DKH;

    const int lrow  = lane & 15;
    const int lhalf = lane >> 4;

    // ---- stage Q (256 x 64): hi -> stage0 region, lo -> stage1 region ----
    {
        const __nv_bfloat16* Qh = g_qhi + base + (size_t)q0 * DKH;
        const __nv_bfloat16* Ql = g_qlo + base + (size_t)q0 * DKH;
        #pragma unroll
        for (int l = 0; l < 8; l++) {
            int idx = tid + l * 256;
            int r = idx >> 3, c = idx & 7;
            uint32_t dof = (uint32_t)(r * AROWB + c * 16);
            size_t   sof = ((size_t)r * DKH) * 2 + c * 16;
            cpasync16(smem_base + dof,       (const char*)Qh + sof);
            cpasync16(smem_base + AST + dof, (const char*)Ql + sof);
        }
        CP_COMMIT();
        CP_WAIT0();
    }
    __syncthreads();

    uint32_t qhi[2][4][4], qlo[2][4][4];   // [am][ks][regs]
    #pragma unroll
    for (int am = 0; am < 2; am++) {
        const uint32_t qa = smem_base +
            (uint32_t)((w * 32 + am * 16 + lrow) * AROWB + lhalf * 16);
        #pragma unroll
        for (int ks = 0; ks < 4; ks++) {
            ldsm_x4(qa + ks * 32, qhi[am][ks]);
            ldsm_x4(qa + AST + ks * 32, qlo[am][ks]);
        }
    }
    __syncthreads();     // all warps done reading Q
    attn_load_stage(smem_base, base, tid);
    CP_COMMIT();
    attn_load_stage(smem_base + AST, base + (size_t)64 * DKH, tid);
    CP_COMMIT();

    float o[2][8][4] = {};
    float m[2][2], l[2][2];
    #pragma unroll
    for (int am = 0; am < 2; am++) {
        m[am][0] = -1e30f; m[am][1] = -1e30f;
        l[am][0] = 0.0f;   l[am][1] = 0.0f;
    }

    const uint32_t lane_off = (uint32_t)(lrow * AROWB + lhalf * 16);

    for (int ch = 0; ch < 32; ch++) {
        if (ch >= 30) { CP_WAIT0(); } else { CP_WAIT1(); }
        __syncthreads();
        const uint32_t st = smem_base + (uint32_t)(ch & 1) * AST;
        const uint32_t kb = st + lane_off;

        // ---- S = Q K^T : 32 x 64 per warp, 3-pass, bn processed in pairs ----
        float s[2][8][4] = {};
        #pragma unroll
        for (int ks = 0; ks < 4; ks++) {
            const uint32_t koff = ks * 32;
            #pragma unroll
            for (int bnp = 0; bnp < 2; bnp++) {
                uint32_t kh[2][4], kl[2][4];
                #pragma unroll
                for (int b = 0; b < 2; b++) {
                    const int bn = bnp * 2 + b;
                    ldsm_x4(kb + 0 * ATILE + bn * 16 * AROWB + koff, kh[b]);
                    ldsm_x4(kb + 1 * ATILE + bn * 16 * AROWB + koff, kl[b]);
                }
                // pass 1: qhi x khi  (8 independent MMAs)
                #pragma unroll
                for (int b = 0; b < 2; b++)
                    #pragma unroll
                    for (int am = 0; am < 2; am++) {
                        const int bn = bnp * 2 + b;
                        mma_bf16(s[am][2*bn],   qhi[am][ks], kh[b][0], kh[b][2]);
                        mma_bf16(s[am][2*bn+1], qhi[am][ks], kh[b][1], kh[b][3]);
                    }
                // pass 2: qhi x klo
                #pragma unroll
                for (int b = 0; b < 2; b++)
                    #pragma unroll
                    for (int am = 0; am < 2; am++) {
                        const int bn = bnp * 2 + b;
                        mma_bf16(s[am][2*bn],   qhi[am][ks], kl[b][0], kl[b][2]);
                        mma_bf16(s[am][2*bn+1], qhi[am][ks], kl[b][1], kl[b][3]);
                    }
                // pass 3: qlo x khi
                #pragma unroll
                for (int b = 0; b < 2; b++)
                    #pragma unroll
                    for (int am = 0; am < 2; am++) {
                        const int bn = bnp * 2 + b;
                        mma_bf16(s[am][2*bn],   qlo[am][ks], kh[b][0], kh[b][2]);
                        mma_bf16(s[am][2*bn+1], qlo[am][ks], kh[b][1], kh[b][3]);
                    }
            }
        }

        // ---- online softmax per am group ----
        #pragma unroll
        for (int am = 0; am < 2; am++) {
            float mxA = -1e30f, mxB = -1e30f;
            #pragma unroll
            for (int j = 0; j < 8; j++) {
                mxA = fmaxf(mxA, fmaxf(s[am][j][0], s[am][j][1]));
                mxB = fmaxf(mxB, fmaxf(s[am][j][2], s[am][j][3]));
            }
            #pragma unroll
            for (int msk = 1; msk < 4; msk <<= 1) {
                mxA = fmaxf(mxA, __shfl_xor_sync(0xffffffffu, mxA, msk));
                mxB = fmaxf(mxB, __shfl_xor_sync(0xffffffffu, mxB, msk));
            }
            const float mnA = fmaxf(m[am][0], mxA);
            const float mnB = fmaxf(m[am][1], mxB);
            const float fA = __expf(m[am][0] - mnA);
            const float fB = __expf(m[am][1] - mnB);
            m[am][0] = mnA; m[am][1] = mnB;
            float rsA = 0.0f, rsB = 0.0f;
            #pragma unroll
            for (int j = 0; j < 8; j++) {
                s[am][j][0] = __expf(s[am][j][0] - mnA); rsA += s[am][j][0];
                s[am][j][1] = __expf(s[am][j][1] - mnA); rsA += s[am][j][1];
                s[am][j][2] = __expf(s[am][j][2] - mnB); rsB += s[am][j][2];
                s[am][j][3] = __expf(s[am][j][3] - mnB); rsB += s[am][j][3];
            }
            #pragma unroll
            for (int msk = 1; msk < 4; msk <<= 1) {
                rsA += __shfl_xor_sync(0xffffffffu, rsA, msk);
                rsB += __shfl_xor_sync(0xffffffffu, rsB, msk);
            }
            l[am][0] = l[am][0] * fA + rsA;
            l[am][1] = l[am][1] * fB + rsB;
            #pragma unroll
            for (int j = 0; j < 8; j++) {
                o[am][j][0] *= fA; o[am][j][1] *= fA;
                o[am][j][2] *= fB; o[am][j][3] *= fB;
            }
        }

        // ---- O += P V : dvp processed in pairs, pass-major ----
        #pragma unroll
        for (int j = 0; j < 4; j++) {
            uint32_t ph[2][4], pl[2][4];
            #pragma unroll
            for (int am = 0; am < 2; am++) {
                __nv_bfloat16 hb[8]; float lw[8];
                split2(s[am][2*j][0],   hb[0], lw[0]);
                split2(s[am][2*j][1],   hb[1], lw[1]);
                split2(s[am][2*j][2],   hb[2], lw[2]);
                split2(s[am][2*j][3],   hb[3], lw[3]);
                split2(s[am][2*j+1][0], hb[4], lw[4]);
                split2(s[am][2*j+1][1], hb[5], lw[5]);
                split2(s[am][2*j+1][2], hb[6], lw[6]);
                split2(s[am][2*j+1][3], hb[7], lw[7]);
                union { __nv_bfloat162 b2; uint32_t u; } t;
                t.b2 = __nv_bfloat162(hb[0], hb[1]); ph[am][0] = t.u;
                t.b2 = __nv_bfloat162(hb[2], hb[3]); ph[am][1] = t.u;
                t.b2 = __nv_bfloat162(hb[4], hb[5]); ph[am][2] = t.u;
                t.b2 = __nv_bfloat162(hb[6], hb[7]); ph[am][3] = t.u;
                pl[am][0] = pkbf(lw[0], lw[1]);
                pl[am][1] = pkbf(lw[2], lw[3]);
                pl[am][2] = pkbf(lw[4], lw[5]);
                pl[am][3] = pkbf(lw[6], lw[7]);
            }
            const uint32_t vrow = st + (uint32_t)((j * 16 + lrow) * AROWB + lhalf * 16);
            #pragma unroll
            for (int dvpp = 0; dvpp < 2; dvpp++) {
                uint32_t vh[2][4], vl[2][4];
                #pragma unroll
                for (int d = 0; d < 2; d++) {
                    const int dvp = dvpp * 2 + d;
                    ldsm_x4_t(vrow + 2 * ATILE + dvp * 32, vh[d]);
                    ldsm_x4_t(vrow + 3 * ATILE + dvp * 32, vl[d]);
                }
                // pass 1: ph x vh  (8 independent MMAs)
                #pragma unroll
                for (int d = 0; d < 2; d++)
                    #pragma unroll
                    for (int am = 0; am < 2; am++) {
                        const int dvp = dvpp * 2 + d;
                        mma_bf16(o[am][2*dvp],   ph[am], vh[d][0], vh[d][1]);
                        mma_bf16(o[am][2*dvp+1], ph[am], vh[d][2], vh[d][3]);
                    }
                // pass 2: ph x vl
                #pragma unroll
                for (int d = 0; d < 2; d++)
                    #pragma unroll
                    for (int am = 0; am < 2; am++) {
                        const int dvp = dvpp * 2 + d;
                        mma_bf16(o[am][2*dvp],   ph[am], vl[d][0], vl[d][1]);
                        mma_bf16(o[am][2*dvp+1], ph[am], vl[d][2], vl[d][3]);
                    }
                // pass 3: pl x vh
                #pragma unroll
                for (int d = 0; d < 2; d++)
                    #pragma unroll
                    for (int am = 0; am < 2; am++) {
                        const int dvp = dvpp * 2 + d;
                        mma_bf16(o[am][2*dvp],   pl[am], vh[d][0], vh[d][1]);
                        mma_bf16(o[am][2*dvp+1], pl[am], vh[d][2], vh[d][3]);
                    }
            }
        }
        __syncthreads();
        if (ch + 2 < 32) {
            attn_load_stage(smem_base + (uint32_t)(ch & 1) * AST,
                            base + (size_t)((ch + 2) * 64) * DKH, tid);
            CP_COMMIT();
        }
    }

    // ---- epilogue: normalize, split hi/lo, write ctx [token][1024] ----
    const int b_ = bh / HH;
    const int h_ = bh % HH;
    #pragma unroll
    for (int am = 0; am < 2; am++) {
        const float invA = 1.0f / l[am][0];
        const float invB = 1.0f / l[am][1];
        const int rA = q0 + w * 32 + am * 16 + (lane >> 2);
        const int tokenA = b_ * SS + rA;
        const int tokenB = tokenA + 8;
        #pragma unroll
        for (int jj = 0; jj < 8; jj++) {
            const int col = h_ * DKH + jj * 8 + (lane & 3) * 2;
            {
                float v0 = o[am][jj][0] * invA, v1 = o[am][jj][1] * invA;
                __nv_bfloat16 h0, h1; float l0, l1;
                split2(v0, h0, l0); split2(v1, h1, l1);
                size_t idx = (size_t)tokenA * DD + col;
                *(__nv_bfloat162*)&g_chi[idx] = __nv_bfloat162(h0, h1);
                *(__nv_bfloat162*)&g_clo[idx] =
                    __nv_bfloat162(__float2bfloat16(l0), __float2bfloat16(l1));
            }
            {
                float v0 = o[am][jj][2] * invB, v1 = o[am][jj][3] * invB;
                __nv_bfloat16 h0, h1; float l0, l1;
                split2(v0, h0, l0); split2(v1, h1, l1);
                size_t idx = (size_t)tokenB * DD + col;
                *(__nv_bfloat162*)&g_chi[idx] = __nv_bfloat162(h0, h1);
                *(__nv_bfloat162*)&g_clo[idx] =
                    __nv_bfloat162(__float2bfloat16(l0), __float2bfloat16(l1));
            }
        }
    }
}

// ---------------------------------------------------------------------------
extern "C" void kernel_launch(void* const* d_in, const int* in_sizes, int n_in,
                              void* d_out, int out_size)
{
    const float* X  = (const float*)d_in[0];
    const float* Wq = (const float*)d_in[1];
    const float* bq = (const float*)d_in[2];
    const float* Wk = (const float*)d_in[3];
    const float* bk = (const float*)d_in[4];
    const float* Wv = (const float*)d_in[5];
    const float* bv = (const float*)d_in[6];
    const float* Wo = (const float*)d_in[7];
    const float* bo = (const float*)d_in[8];
    float* out = (float*)d_out;

    cudaFuncSetAttribute(qkv_mma_kernel,
                         cudaFuncAttributeMaxDynamicSharedMemorySize, GSM_BYTES);
    cudaFuncSetAttribute(out_mma_kernel,
                         cudaFuncAttributeMaxDynamicSharedMemorySize, GSM_BYTES);
    cudaFuncSetAttribute(attn_mma_kernel,
                         cudaFuncAttributeMaxDynamicSharedMemorySize, ATTN_SM_BYTES);

    conv_x_kernel<<<2048, 256>>>((const float4*)X);
    conv_w_kernel<<<dim3(16, 16, 3), 256>>>(Wq, Wk, Wv);
    conv_wo_kernel<<<dim3(16, 16), 256>>>(Wo);
    qkv_mma_kernel<<<dim3(32, 8, 3), 256, GSM_BYTES>>>(bq, bk, bv);
    attn_mma_kernel<<<dim3(8, 32), 256, ATTN_SM_BYTES>>>();
    out_mma_kernel<<<dim3(32, 8), 256, GSM_BYTES>>>(bo, out);
}

// round 11
// speedup vs baseline: 1.4737x; 1.4737x over previous
#include <cuda_runtime.h>
#include <cuda_fp16.h>
#include <cstdint>

#define BB 2
#define SS 2048
#define DD 1024
#define HH 16
#define DKH 64
#define BHH (BB*HH)

// ---------------------------------------------------------------------------
// Scratch (allocation-free rule: __device__ globals)
// A-side operands split hi/lo fp16 (22-bit); B-side single fp16.
// ---------------------------------------------------------------------------
__device__ __half g_xhi[BB * SS * DD];
__device__ __half g_xlo[BB * SS * DD];
__device__ __half g_w  [3 * HH * DKH * DD];   // [(proj*16+h)*64+n][k]
__device__ __half g_qhi[BHH * SS * DKH];      // [bh][s][64] (UNscaled)
__device__ __half g_qlo[BHH * SS * DKH];
__device__ __half g_k  [BHH * SS * DKH];
__device__ __half g_v  [BHH * SS * DKH];
__device__ __half g_chi[BB * SS * HH * DKH];  // ctx [token][1024]
__device__ __half g_clo[BB * SS * HH * DKH];
__device__ __half g_wo [DD * DD];             // Wo^T [n][k]

// ---------------------------------------------------------------------------
// Helpers
// ---------------------------------------------------------------------------
__device__ __forceinline__ uint32_t smem_to_u32(const void* p) {
    uint32_t a;
    asm("{ .reg .u64 t; cvta.to.shared.u64 t, %1; cvt.u32.u64 %0, t; }"
        : "=r"(a) : "l"(p));
    return a;
}
__device__ __forceinline__ void ldsm_x4(uint32_t addr, uint32_t* r) {
    asm volatile("ldmatrix.sync.aligned.m8n8.x4.shared.b16 {%0,%1,%2,%3}, [%4];"
        : "=r"(r[0]), "=r"(r[1]), "=r"(r[2]), "=r"(r[3]) : "r"(addr));
}
__device__ __forceinline__ void ldsm_x4_t(uint32_t addr, uint32_t* r) {
    asm volatile("ldmatrix.sync.aligned.m8n8.x4.trans.shared.b16 {%0,%1,%2,%3}, [%4];"
        : "=r"(r[0]), "=r"(r[1]), "=r"(r[2]), "=r"(r[3]) : "r"(addr));
}
__device__ __forceinline__ void mma_f16(float* d, const uint32_t* a,
                                        uint32_t b0, uint32_t b1) {
    asm volatile(
        "mma.sync.aligned.m16n8k16.row.col.f32.f16.f16.f32 "
        "{%0,%1,%2,%3}, {%4,%5,%6,%7}, {%8,%9}, {%0,%1,%2,%3};"
        : "+f"(d[0]), "+f"(d[1]), "+f"(d[2]), "+f"(d[3])
        : "r"(a[0]), "r"(a[1]), "r"(a[2]), "r"(a[3]), "r"(b0), "r"(b1));
}
__device__ __forceinline__ uint32_t pkh(float lo, float hi) {
    uint32_t r;
    asm("cvt.rn.f16x2.f32 %0, %1, %2;" : "=r"(r) : "f"(hi), "f"(lo));
    return r;
}
__device__ __forceinline__ void split2h(float v, __half& h, float& l) {
    h = __float2half_rn(v);
    l = v - __half2float(h);
}
__device__ __forceinline__ void cpasync16(uint32_t dst, const void* src) {
    asm volatile("cp.async.cg.shared.global [%0], [%1], 16;"
                 :: "r"(dst), "l"(src));
}
#define CP_COMMIT() asm volatile("cp.async.commit_group;" ::: "memory")
#define CP_WAIT1()  asm volatile("cp.async.wait_group 1;" ::: "memory")
#define CP_WAIT0()  asm volatile("cp.async.wait_group 0;" ::: "memory")

// ---------------------------------------------------------------------------
// Prep A: split X into fp16 hi/lo.
// ---------------------------------------------------------------------------
__global__ __launch_bounds__(256) void conv_x_kernel(const float4* __restrict__ X4)
{
    int i0 = blockIdx.x * 256 + threadIdx.x;
    #pragma unroll
    for (int l = 0; l < 2; l++) {
        int i = i0 + l * 524288;
        float4 v = X4[i];
        float vv[4] = {v.x, v.y, v.z, v.w};
        union { float2 f; __half h[4]; } hi, lo;
        #pragma unroll
        for (int j = 0; j < 4; j++) {
            float lw; split2h(vv[j], hi.h[j], lw);
            lo.h[j] = __float2half_rn(lw);
        }
        ((float2*)g_xhi)[i] = hi.f;
        ((float2*)g_xlo)[i] = lo.f;
    }
}

// ---------------------------------------------------------------------------
// Prep B: transpose Wq/Wk/Wv -> single fp16 [(proj*16+h)*64+n][k].
// ---------------------------------------------------------------------------
__global__ __launch_bounds__(256) void conv_w_kernel(
    const float* __restrict__ Wq, const float* __restrict__ Wk,
    const float* __restrict__ Wv)
{
    __shared__ float ts[64][65];
    const int k0   = blockIdx.x * 64;
    const int h    = blockIdx.y;
    const int proj = blockIdx.z;
    const float* W = (proj == 0) ? Wq : (proj == 1) ? Wk : Wv;
    W += (size_t)h * DD * DKH;

    const int tid = threadIdx.x;
    #pragma unroll
    for (int l = 0; l < 4; l++) {
        int idx = tid + l * 256;
        int r = idx >> 4, c4 = idx & 15;
        float4 v = *(const float4*)&W[(size_t)(k0 + r) * DKH + c4 * 4];
        ts[r][c4 * 4 + 0] = v.x;
        ts[r][c4 * 4 + 1] = v.y;
        ts[r][c4 * 4 + 2] = v.z;
        ts[r][c4 * 4 + 3] = v.w;
    }
    __syncthreads();
    #pragma unroll
    for (int l = 0; l < 4; l++) {
        int idx = tid + l * 256;
        int nr = idx >> 4, kc = idx & 15;
        size_t orow = ((size_t)(proj * HH + h) * DKH + nr) * DD + k0 + kc * 4;
        #pragma unroll
        for (int j = 0; j < 4; j++)
            g_w[orow + j] = __float2half_rn(ts[kc * 4 + j][nr]);
    }
}

// ---------------------------------------------------------------------------
// Prep C: transpose Wo -> single fp16 [n][k].
// ---------------------------------------------------------------------------
__global__ __launch_bounds__(256) void conv_wo_kernel(const float* __restrict__ Wo)
{
    __shared__ float ts[64][65];
    const int k0 = blockIdx.x * 64;
    const int n0 = blockIdx.y * 64;
    const int tid = threadIdx.x;
    #pragma unroll
    for (int l = 0; l < 4; l++) {
        int idx = tid + l * 256;
        int r = idx >> 4, c4 = idx & 15;
        float4 v = *(const float4*)&Wo[(size_t)(k0 + r) * DD + n0 + c4 * 4];
        ts[r][c4 * 4 + 0] = v.x;
        ts[r][c4 * 4 + 1] = v.y;
        ts[r][c4 * 4 + 2] = v.z;
        ts[r][c4 * 4 + 3] = v.w;
    }
    __syncthreads();
    #pragma unroll
    for (int l = 0; l < 4; l++) {
        int idx = tid + l * 256;
        int nr = idx >> 4, kc = idx & 15;
        size_t orow = (size_t)(n0 + nr) * DD + k0 + kc * 4;
        #pragma unroll
        for (int j = 0; j < 4; j++)
            g_wo[orow + j] = __float2half_rn(ts[kc * 4 + j][nr]);
    }
}

// ---------------------------------------------------------------------------
// Pipelined GEMM: M128 x N128 CTA, K chunks of 32, 2 stages, 3 tiles/stage
// (AHI | ALO | B). Warp tile 64x32 (2M x 4N). 2 CTAs/SM (regs <= 128).
// 2-pass fp16: acc += Ahi*B ; acc += Alo*B.
// ---------------------------------------------------------------------------
#define CROWB 80
#define CTILE (128 * CROWB)       // 10240
#define CSTAGE (3 * CTILE)        // 30720
#define GSM_BYTES (2 * CSTAGE)    // 61440

__device__ __forceinline__ void load_stage_g(
    uint32_t sm,
    const __half* __restrict__ Ahi, const __half* __restrict__ Alo,
    const __half* __restrict__ B, int k0, int tid)
{
    #pragma unroll
    for (int l = 0; l < 2; l++) {
        int idx = tid + l * 256;
        int r = idx >> 2, c = idx & 3;
        uint32_t dof = (uint32_t)(r * CROWB + c * 16);
        size_t   sof = ((size_t)r * DD + k0) * 2 + c * 16;
        cpasync16(sm + 0 * CTILE + dof, (const char*)Ahi + sof);
        cpasync16(sm + 1 * CTILE + dof, (const char*)Alo + sof);
        cpasync16(sm + 2 * CTILE + dof, (const char*)B   + sof);
    }
}

__device__ __forceinline__ void gemm_body(
    uint32_t smem_base, uint32_t a_lane, uint32_t b_lane,
    const __half* Ahi, const __half* Alo, const __half* B,
    int tid, float acc[4][4][4])
{
    load_stage_g(smem_base,          Ahi, Alo, B, 0,  tid);
    CP_COMMIT();
    load_stage_g(smem_base + CSTAGE, Ahi, Alo, B, 32, tid);
    CP_COMMIT();

    for (int ch = 0; ch < 32; ch++) {
        if (ch >= 30) { CP_WAIT0(); } else { CP_WAIT1(); }
        __syncthreads();
        const uint32_t st = smem_base + (uint32_t)(ch & 1) * CSTAGE;

        #pragma unroll
        for (int ks = 0; ks < 2; ks++) {
            const uint32_t koff = ks * 32;
            uint32_t ahi[4][4], alo[4][4];
            #pragma unroll
            for (int am = 0; am < 4; am++) {
                ldsm_x4(st + 0 * CTILE + a_lane + am * 16 * CROWB + koff, ahi[am]);
                ldsm_x4(st + 1 * CTILE + a_lane + am * 16 * CROWB + koff, alo[am]);
            }
            uint32_t b[2][4];
            #pragma unroll
            for (int bn = 0; bn < 2; bn++)
                ldsm_x4(st + 2 * CTILE + b_lane + bn * 16 * CROWB + koff, b[bn]);

            // pass 1: ahi x b (16 independent MMAs)
            #pragma unroll
            for (int am = 0; am < 4; am++)
                #pragma unroll
                for (int bn = 0; bn < 2; bn++) {
                    mma_f16(acc[am][2*bn],   ahi[am], b[bn][0], b[bn][2]);
                    mma_f16(acc[am][2*bn+1], ahi[am], b[bn][1], b[bn][3]);
                }
            // pass 2: alo x b
            #pragma unroll
            for (int am = 0; am < 4; am++)
                #pragma unroll
                for (int bn = 0; bn < 2; bn++) {
                    mma_f16(acc[am][2*bn],   alo[am], b[bn][0], b[bn][2]);
                    mma_f16(acc[am][2*bn+1], alo[am], b[bn][1], b[bn][3]);
                }
        }
        __syncthreads();
        if (ch + 2 < 32) {
            load_stage_g(smem_base + (uint32_t)(ch & 1) * CSTAGE,
                         Ahi, Alo, B, (ch + 2) * 32, tid);
            CP_COMMIT();
        }
    }
}

// ---------------------------------------------------------------------------
// QKV GEMM: Q -> hi/lo fp16 (unscaled); K, V -> single fp16.
// ---------------------------------------------------------------------------
__global__ __launch_bounds__(256, 2) void qkv_mma_kernel(
    const float* __restrict__ bq, const float* __restrict__ bk,
    const float* __restrict__ bv)
{
    extern __shared__ char smem[];
    const uint32_t smem_base = smem_to_u32(smem);
    const int tid  = threadIdx.x;
    const int lane = tid & 31;
    const int wid  = tid >> 5;
    const int warpM = wid & 1;          // 2 groups x 64 rows
    const int warpN = wid >> 1;         // 4 groups x 32 cols

    const int m0   = blockIdx.x * 128;
    const int hg   = blockIdx.y;
    const int proj = blockIdx.z;

    const float* bias = (proj == 0) ? bq : (proj == 1) ? bk : bv;
    __half* ohi = (proj == 0) ? g_qhi : (proj == 1) ? g_k : g_v;

    const size_t brow = ((size_t)proj * HH * DKH + (size_t)hg * 128) * DD;

    float acc[4][4][4] = {};

    const int lrow  = lane & 15;
    const int lhalf = lane >> 4;
    const uint32_t a_lane = (uint32_t)((warpM * 64 + lrow) * CROWB + lhalf * 16);
    const uint32_t b_lane = (uint32_t)((warpN * 32 + lrow) * CROWB + lhalf * 16);

    gemm_body(smem_base, a_lane, b_lane,
              g_xhi + (size_t)m0 * DD, g_xlo + (size_t)m0 * DD,
              g_w + brow, tid, acc);

    #pragma unroll
    for (int am = 0; am < 4; am++) {
        #pragma unroll
        for (int rh = 0; rh < 2; rh++) {
            const int token = m0 + warpM * 64 + am * 16 + rh * 8 + (lane >> 2);
            const int b_ = token >> 11;
            const int s_ = token & (SS - 1);
            #pragma unroll
            for (int na = 0; na < 4; na++) {
                const int ng = hg * 128 + warpN * 32 + na * 8 + (lane & 3) * 2;
                const int h  = ng >> 6;
                const int dk = ng & 63;
                float v0 = acc[am][na][rh*2+0] + __ldg(&bias[h*DKH + dk]);
                float v1 = acc[am][na][rh*2+1] + __ldg(&bias[h*DKH + dk+1]);
                __half h0, h1; float l0, l1;
                split2h(v0, h0, l0); split2h(v1, h1, l1);
                size_t idx = ((size_t)(b_ * HH + h) * SS + s_) * DKH + dk;
                *(__half2*)&ohi[idx] = __half2(h0, h1);
                if (proj == 0)
                    *(__half2*)&g_qlo[idx] =
                        __half2(__float2half_rn(l0), __float2half_rn(l1));
            }
        }
    }
}

// ---------------------------------------------------------------------------
// Output projection: out = ctx @ Wo + bo (fp32 out). 2 CTAs/SM.
// ---------------------------------------------------------------------------
__global__ __launch_bounds__(256, 2) void out_mma_kernel(
    const float* __restrict__ bo, float* __restrict__ out)
{
    extern __shared__ char smem[];
    const uint32_t smem_base = smem_to_u32(smem);
    const int tid  = threadIdx.x;
    const int lane = tid & 31;
    const int wid  = tid >> 5;
    const int warpM = wid & 1;
    const int warpN = wid >> 1;

    const int m0 = blockIdx.x * 128;
    const int n0 = blockIdx.y * 128;

    float acc[4][4][4] = {};

    const int lrow  = lane & 15;
    const int lhalf = lane >> 4;
    const uint32_t a_lane = (uint32_t)((warpM * 64 + lrow) * CROWB + lhalf * 16);
    const uint32_t b_lane = (uint32_t)((warpN * 32 + lrow) * CROWB + lhalf * 16);

    gemm_body(smem_base, a_lane, b_lane,
              g_chi + (size_t)m0 * DD, g_clo + (size_t)m0 * DD,
              g_wo + (size_t)n0 * DD, tid, acc);

    #pragma unroll
    for (int am = 0; am < 4; am++) {
        #pragma unroll
        for (int rh = 0; rh < 2; rh++) {
            const int token = m0 + warpM * 64 + am * 16 + rh * 8 + (lane >> 2);
            #pragma unroll
            for (int na = 0; na < 4; na++) {
                const int n = n0 + warpN * 32 + na * 8 + (lane & 3) * 2;
                float2 o;
                o.x = acc[am][na][rh*2+0] + __ldg(&bo[n]);
                o.y = acc[am][na][rh*2+1] + __ldg(&bo[n+1]);
                *(float2*)&out[(size_t)token * DD + n] = o;
            }
        }
    }
}

// ---------------------------------------------------------------------------
// Flash attention: 32 q-rows/warp (q-tile 256), grid (8, 32), block 256.
// K/V single fp16 (2 tiles/stage, 2 stages). Q split fp16 resident in regs.
// Scores scaled by 0.125 in fp32 after MMA.
// ---------------------------------------------------------------------------
#define AROWB 144                    // 72 fp16 per row
#define ATILE (64 * AROWB)           // 9216
#define AST (2 * ATILE)              // 18432 : K | V
#define ATTN_SM_BYTES (2 * AST)      // 36864

__device__ __forceinline__ void attn_load_stage(
    uint32_t sm, size_t key0, int tid)
{
    #pragma unroll
    for (int l = 0; l < 2; l++) {
        int idx = tid + l * 256;
        int r = idx >> 3, c = idx & 7;
        uint32_t dof = (uint32_t)(r * AROWB + c * 16);
        size_t   sof = ((size_t)r * DKH) * 2 + c * 16;
        cpasync16(sm + 0 * ATILE + dof, (const char*)(g_k + key0) + sof);
        cpasync16(sm + 1 * ATILE + dof, (const char*)(g_v + key0) + sof);
    }
}

__global__ __launch_bounds__(256, 1) void attn_mma_kernel()
{
    extern __shared__ char smem[];
    const uint32_t smem_base = smem_to_u32(smem);
    const int tid  = threadIdx.x;
    const int lane = tid & 31;
    const int w    = tid >> 5;          // warp 0..7 -> q rows w*32..w*32+31

    const int bh = blockIdx.y;
    const int q0 = blockIdx.x * 256;
    const size_t base = (size_t)bh * SS * DKH;

    const int lrow  = lane & 15;
    const int lhalf = lane >> 4;

    // ---- stage Q in two phases (hi then lo) through the whole smem ----
    uint32_t qhi[2][4][4], qlo[2][4][4];   // [am][ks][regs]
    #pragma unroll
    for (int phase = 0; phase < 2; phase++) {
        const __half* Qp = (phase == 0 ? g_qhi : g_qlo) + base + (size_t)q0 * DKH;
        #pragma unroll
        for (int l = 0; l < 8; l++) {
            int idx = tid + l * 256;
            int r = idx >> 3, c = idx & 7;
            cpasync16(smem_base + (uint32_t)(r * AROWB + c * 16),
                      (const char*)Qp + ((size_t)r * DKH) * 2 + c * 16);
        }
        CP_COMMIT();
        CP_WAIT0();
        __syncthreads();
        #pragma unroll
        for (int am = 0; am < 2; am++) {
            const uint32_t qa = smem_base +
                (uint32_t)((w * 32 + am * 16 + lrow) * AROWB + lhalf * 16);
            #pragma unroll
            for (int ks = 0; ks < 4; ks++) {
                if (phase == 0) ldsm_x4(qa + ks * 32, qhi[am][ks]);
                else            ldsm_x4(qa + ks * 32, qlo[am][ks]);
            }
        }
        __syncthreads();
    }

    attn_load_stage(smem_base, base, tid);
    CP_COMMIT();
    attn_load_stage(smem_base + AST, base + (size_t)64 * DKH, tid);
    CP_COMMIT();

    float o[2][8][4] = {};
    float m[2][2], l[2][2];
    #pragma unroll
    for (int am = 0; am < 2; am++) {
        m[am][0] = -1e30f; m[am][1] = -1e30f;
        l[am][0] = 0.0f;   l[am][1] = 0.0f;
    }

    const uint32_t lane_off = (uint32_t)(lrow * AROWB + lhalf * 16);

    for (int ch = 0; ch < 32; ch++) {
        if (ch >= 30) { CP_WAIT0(); } else { CP_WAIT1(); }
        __syncthreads();
        const uint32_t st = smem_base + (uint32_t)(ch & 1) * AST;
        const uint32_t kb = st + lane_off;

        // ---- S = Q K^T : 32 x 64 per warp, 2-pass ----
        float s[2][8][4] = {};
        #pragma unroll
        for (int ks = 0; ks < 4; ks++) {
            const uint32_t koff = ks * 32;
            uint32_t kh[4][4];
            #pragma unroll
            for (int bn = 0; bn < 4; bn++)
                ldsm_x4(kb + bn * 16 * AROWB + koff, kh[bn]);
            // pass 1: qhi x k (16 independent MMAs)
            #pragma unroll
            for (int bn = 0; bn < 4; bn++)
                #pragma unroll
                for (int am = 0; am < 2; am++) {
                    mma_f16(s[am][2*bn],   qhi[am][ks], kh[bn][0], kh[bn][2]);
                    mma_f16(s[am][2*bn+1], qhi[am][ks], kh[bn][1], kh[bn][3]);
                }
            // pass 2: qlo x k
            #pragma unroll
            for (int bn = 0; bn < 4; bn++)
                #pragma unroll
                for (int am = 0; am < 2; am++) {
                    mma_f16(s[am][2*bn],   qlo[am][ks], kh[bn][0], kh[bn][2]);
                    mma_f16(s[am][2*bn+1], qlo[am][ks], kh[bn][1], kh[bn][3]);
                }
        }
        // fold the 1/sqrt(dk) scale in fp32
        #pragma unroll
        for (int am = 0; am < 2; am++)
            #pragma unroll
            for (int j = 0; j < 8; j++)
                #pragma unroll
                for (int c = 0; c < 4; c++)
                    s[am][j][c] *= 0.125f;

        // ---- online softmax per am group ----
        #pragma unroll
        for (int am = 0; am < 2; am++) {
            float mxA = -1e30f, mxB = -1e30f;
            #pragma unroll
            for (int j = 0; j < 8; j++) {
                mxA = fmaxf(mxA, fmaxf(s[am][j][0], s[am][j][1]));
                mxB = fmaxf(mxB, fmaxf(s[am][j][2], s[am][j][3]));
            }
            #pragma unroll
            for (int msk = 1; msk < 4; msk <<= 1) {
                mxA = fmaxf(mxA, __shfl_xor_sync(0xffffffffu, mxA, msk));
                mxB = fmaxf(mxB, __shfl_xor_sync(0xffffffffu, mxB, msk));
            }
            const float mnA = fmaxf(m[am][0], mxA);
            const float mnB = fmaxf(m[am][1], mxB);
            const float fA = __expf(m[am][0] - mnA);
            const float fB = __expf(m[am][1] - mnB);
            m[am][0] = mnA; m[am][1] = mnB;
            float rsA = 0.0f, rsB = 0.0f;
            #pragma unroll
            for (int j = 0; j < 8; j++) {
                s[am][j][0] = __expf(s[am][j][0] - mnA); rsA += s[am][j][0];
                s[am][j][1] = __expf(s[am][j][1] - mnA); rsA += s[am][j][1];
                s[am][j][2] = __expf(s[am][j][2] - mnB); rsB += s[am][j][2];
                s[am][j][3] = __expf(s[am][j][3] - mnB); rsB += s[am][j][3];
            }
            #pragma unroll
            for (int msk = 1; msk < 4; msk <<= 1) {
                rsA += __shfl_xor_sync(0xffffffffu, rsA, msk);
                rsB += __shfl_xor_sync(0xffffffffu, rsB, msk);
            }
            l[am][0] = l[am][0] * fA + rsA;
            l[am][1] = l[am][1] * fB + rsB;
            #pragma unroll
            for (int j = 0; j < 8; j++) {
                o[am][j][0] *= fA; o[am][j][1] *= fA;
                o[am][j][2] *= fB; o[am][j][3] *= fB;
            }
        }

        // ---- O += P V : P split hi/lo in regs, V single, 2-pass ----
        #pragma unroll
        for (int j = 0; j < 4; j++) {
            uint32_t ph[2][4], pl[2][4];
            #pragma unroll
            for (int am = 0; am < 2; am++) {
                __half hb[8]; float lw[8];
                split2h(s[am][2*j][0],   hb[0], lw[0]);
                split2h(s[am][2*j][1],   hb[1], lw[1]);
                split2h(s[am][2*j][2],   hb[2], lw[2]);
                split2h(s[am][2*j][3],   hb[3], lw[3]);
                split2h(s[am][2*j+1][0], hb[4], lw[4]);
                split2h(s[am][2*j+1][1], hb[5], lw[5]);
                split2h(s[am][2*j+1][2], hb[6], lw[6]);
                split2h(s[am][2*j+1][3], hb[7], lw[7]);
                union { __half2 b2; uint32_t u; } t;
                t.b2 = __half2(hb[0], hb[1]); ph[am][0] = t.u;
                t.b2 = __half2(hb[2], hb[3]); ph[am][1] = t.u;
                t.b2 = __half2(hb[4], hb[5]); ph[am][2] = t.u;
                t.b2 = __half2(hb[6], hb[7]); ph[am][3] = t.u;
                pl[am][0] = pkh(lw[0], lw[1]);
                pl[am][1] = pkh(lw[2], lw[3]);
                pl[am][2] = pkh(lw[4], lw[5]);
                pl[am][3] = pkh(lw[6], lw[7]);
            }
            const uint32_t vrow = st + 1 * ATILE +
                (uint32_t)((j * 16 + lrow) * AROWB + lhalf * 16);
            uint32_t vh[4][4];
            #pragma unroll
            for (int dvp = 0; dvp < 4; dvp++)
                ldsm_x4_t(vrow + dvp * 32, vh[dvp]);
            // pass 1: ph x v (16 independent MMAs)
            #pragma unroll
            for (int dvp = 0; dvp < 4; dvp++)
                #pragma unroll
                for (int am = 0; am < 2; am++) {
                    mma_f16(o[am][2*dvp],   ph[am], vh[dvp][0], vh[dvp][1]);
                    mma_f16(o[am][2*dvp+1], ph[am], vh[dvp][2], vh[dvp][3]);
                }
            // pass 2: pl x v
            #pragma unroll
            for (int dvp = 0; dvp < 4; dvp++)
                #pragma unroll
                for (int am = 0; am < 2; am++) {
                    mma_f16(o[am][2*dvp],   pl[am], vh[dvp][0], vh[dvp][1]);
                    mma_f16(o[am][2*dvp+1], pl[am], vh[dvp][2], vh[dvp][3]);
                }
        }
        __syncthreads();
        if (ch + 2 < 32) {
            attn_load_stage(smem_base + (uint32_t)(ch & 1) * AST,
                            base + (size_t)((ch + 2) * 64) * DKH, tid);
            CP_COMMIT();
        }
    }

    // ---- epilogue: normalize, split hi/lo, write ctx [token][1024] ----
    const int b_ = bh / HH;
    const int h_ = bh % HH;
    #pragma unroll
    for (int am = 0; am < 2; am++) {
        const float invA = 1.0f / l[am][0];
        const float invB = 1.0f / l[am][1];
        const int rA = q0 + w * 32 + am * 16 + (lane >> 2);
        const int tokenA = b_ * SS + rA;
        const int tokenB = tokenA + 8;
        #pragma unroll
        for (int jj = 0; jj < 8; jj++) {
            const int col = h_ * DKH + jj * 8 + (lane & 3) * 2;
            {
                float v0 = o[am][jj][0] * invA, v1 = o[am][jj][1] * invA;
                __half h0, h1; float l0, l1;
                split2h(v0, h0, l0); split2h(v1, h1, l1);
                size_t idx = (size_t)tokenA * DD + col;
                *(__half2*)&g_chi[idx] = __half2(h0, h1);
                *(__half2*)&g_clo[idx] =
                    __half2(__float2half_rn(l0), __float2half_rn(l1));
            }
            {
                float v0 = o[am][jj][2] * invB, v1 = o[am][jj][3] * invB;
                __half h0, h1; float l0, l1;
                split2h(v0, h0, l0); split2h(v1, h1, l1);
                size_t idx = (size_t)tokenB * DD + col;
                *(__half2*)&g_chi[idx] = __half2(h0, h1);
                *(__half2*)&g_clo[idx] =
                    __half2(__float2half_rn(l0), __float2half_rn(l1));
            }
        }
    }
}

// ---------------------------------------------------------------------------
extern "C" void kernel_launch(void* const* d_in, const int* in_sizes, int n_in,
                              void* d_out, int out_size)
{
    const float* X  = (const float*)d_in[0];
    const float* Wq = (const float*)d_in[1];
    const float* bq = (const float*)d_in[2];
    const float* Wk = (const float*)d_in[3];
    const float* bk = (const float*)d_in[4];
    const float* Wv = (const float*)d_in[5];
    const float* bv = (const float*)d_in[6];
    const float* Wo = (const float*)d_in[7];
    const float* bo = (const float*)d_in[8];
    float* out = (float*)d_out;

    cudaFuncSetAttribute(qkv_mma_kernel,
                         cudaFuncAttributeMaxDynamicSharedMemorySize, GSM_BYTES);
    cudaFuncSetAttribute(out_mma_kernel,
                         cudaFuncAttributeMaxDynamicSharedMemorySize, GSM_BYTES);
    cudaFuncSetAttribute(attn_mma_kernel,
                         cudaFuncAttributeMaxDynamicSharedMemorySize, ATTN_SM_BYTES);

    conv_x_kernel<<<2048, 256>>>((const float4*)X);
    conv_w_kernel<<<dim3(16, 16, 3), 256>>>(Wq, Wk, Wv);
    conv_wo_kernel<<<dim3(16, 16), 256>>>(Wo);
    qkv_mma_kernel<<<dim3(32, 8, 3), 256, GSM_BYTES>>>(bq, bk, bv);
    attn_mma_kernel<<<dim3(8, 32), 256, ATTN_SM_BYTES>>>();
    out_mma_kernel<<<dim3(32, 8), 256, GSM_BYTES>>>(bo, out);
}

// round 12
// speedup vs baseline: 2.3322x; 1.5826x over previous
#include <cuda_runtime.h>
#include <cuda_fp16.h>
#include <cstdint>

#define BB 2
#define SS 2048
#define DD 1024
#define HH 16
#define DKH 64
#define BHH (BB*HH)

// ---------------------------------------------------------------------------
// Scratch (allocation-free rule: __device__ globals)
// Single fp16 everywhere except Q (hi/lo split: S=QK^T is error-amplifying).
// ---------------------------------------------------------------------------
__device__ __half g_x  [BB * SS * DD];
__device__ __half g_w  [3 * HH * DKH * DD];   // [(proj*16+h)*64+n][k]
__device__ __half g_qhi[BHH * SS * DKH];      // [bh][s][64] (UNscaled)
__device__ __half g_qlo[BHH * SS * DKH];
__device__ __half g_k  [BHH * SS * DKH];
__device__ __half g_v  [BHH * SS * DKH];
__device__ __half g_c  [BB * SS * HH * DKH];  // ctx [token][1024]
__device__ __half g_wo [DD * DD];             // Wo^T [n][k]

// ---------------------------------------------------------------------------
// Helpers
// ---------------------------------------------------------------------------
__device__ __forceinline__ uint32_t smem_to_u32(const void* p) {
    uint32_t a;
    asm("{ .reg .u64 t; cvta.to.shared.u64 t, %1; cvt.u32.u64 %0, t; }"
        : "=r"(a) : "l"(p));
    return a;
}
__device__ __forceinline__ void ldsm_x4(uint32_t addr, uint32_t* r) {
    asm volatile("ldmatrix.sync.aligned.m8n8.x4.shared.b16 {%0,%1,%2,%3}, [%4];"
        : "=r"(r[0]), "=r"(r[1]), "=r"(r[2]), "=r"(r[3]) : "r"(addr));
}
__device__ __forceinline__ void ldsm_x4_t(uint32_t addr, uint32_t* r) {
    asm volatile("ldmatrix.sync.aligned.m8n8.x4.trans.shared.b16 {%0,%1,%2,%3}, [%4];"
        : "=r"(r[0]), "=r"(r[1]), "=r"(r[2]), "=r"(r[3]) : "r"(addr));
}
__device__ __forceinline__ void mma_f16(float* d, const uint32_t* a,
                                        uint32_t b0, uint32_t b1) {
    asm volatile(
        "mma.sync.aligned.m16n8k16.row.col.f32.f16.f16.f32 "
        "{%0,%1,%2,%3}, {%4,%5,%6,%7}, {%8,%9}, {%0,%1,%2,%3};"
        : "+f"(d[0]), "+f"(d[1]), "+f"(d[2]), "+f"(d[3])
        : "r"(a[0]), "r"(a[1]), "r"(a[2]), "r"(a[3]), "r"(b0), "r"(b1));
}
__device__ __forceinline__ uint32_t pkh(float lo, float hi) {
    uint32_t r;
    asm("cvt.rn.f16x2.f32 %0, %1, %2;" : "=r"(r) : "f"(hi), "f"(lo));
    return r;
}
__device__ __forceinline__ void split2h(float v, __half& h, float& l) {
    h = __float2half_rn(v);
    l = v - __half2float(h);
}
__device__ __forceinline__ void cpasync16(uint32_t dst, const void* src) {
    asm volatile("cp.async.cg.shared.global [%0], [%1], 16;"
                 :: "r"(dst), "l"(src));
}
#define CP_COMMIT() asm volatile("cp.async.commit_group;" ::: "memory")
#define CP_WAIT1()  asm volatile("cp.async.wait_group 1;" ::: "memory")
#define CP_WAIT0()  asm volatile("cp.async.wait_group 0;" ::: "memory")

// ---------------------------------------------------------------------------
// Prep A: X -> single fp16.
// ---------------------------------------------------------------------------
__global__ __launch_bounds__(256) void conv_x_kernel(const float4* __restrict__ X4)
{
    int i0 = blockIdx.x * 256 + threadIdx.x;
    #pragma unroll
    for (int l = 0; l < 2; l++) {
        int i = i0 + l * 524288;
        float4 v = X4[i];
        union { float2 f; __half h[4]; } o;
        o.h[0] = __float2half_rn(v.x);
        o.h[1] = __float2half_rn(v.y);
        o.h[2] = __float2half_rn(v.z);
        o.h[3] = __float2half_rn(v.w);
        ((float2*)g_x)[i] = o.f;
    }
}

// ---------------------------------------------------------------------------
// Prep B: transpose Wq/Wk/Wv -> single fp16 [(proj*16+h)*64+n][k].
// ---------------------------------------------------------------------------
__global__ __launch_bounds__(256) void conv_w_kernel(
    const float* __restrict__ Wq, const float* __restrict__ Wk,
    const float* __restrict__ Wv)
{
    __shared__ float ts[64][65];
    const int k0   = blockIdx.x * 64;
    const int h    = blockIdx.y;
    const int proj = blockIdx.z;
    const float* W = (proj == 0) ? Wq : (proj == 1) ? Wk : Wv;
    W += (size_t)h * DD * DKH;

    const int tid = threadIdx.x;
    #pragma unroll
    for (int l = 0; l < 4; l++) {
        int idx = tid + l * 256;
        int r = idx >> 4, c4 = idx & 15;
        float4 v = *(const float4*)&W[(size_t)(k0 + r) * DKH + c4 * 4];
        ts[r][c4 * 4 + 0] = v.x;
        ts[r][c4 * 4 + 1] = v.y;
        ts[r][c4 * 4 + 2] = v.z;
        ts[r][c4 * 4 + 3] = v.w;
    }
    __syncthreads();
    #pragma unroll
    for (int l = 0; l < 4; l++) {
        int idx = tid + l * 256;
        int nr = idx >> 4, kc = idx & 15;
        size_t orow = ((size_t)(proj * HH + h) * DKH + nr) * DD + k0 + kc * 4;
        #pragma unroll
        for (int j = 0; j < 4; j++)
            g_w[orow + j] = __float2half_rn(ts[kc * 4 + j][nr]);
    }
}

// ---------------------------------------------------------------------------
// Prep C: transpose Wo -> single fp16 [n][k].
// ---------------------------------------------------------------------------
__global__ __launch_bounds__(256) void conv_wo_kernel(const float* __restrict__ Wo)
{
    __shared__ float ts[64][65];
    const int k0 = blockIdx.x * 64;
    const int n0 = blockIdx.y * 64;
    const int tid = threadIdx.x;
    #pragma unroll
    for (int l = 0; l < 4; l++) {
        int idx = tid + l * 256;
        int r = idx >> 4, c4 = idx & 15;
        float4 v = *(const float4*)&Wo[(size_t)(k0 + r) * DD + n0 + c4 * 4];
        ts[r][c4 * 4 + 0] = v.x;
        ts[r][c4 * 4 + 1] = v.y;
        ts[r][c4 * 4 + 2] = v.z;
        ts[r][c4 * 4 + 3] = v.w;
    }
    __syncthreads();
    #pragma unroll
    for (int l = 0; l < 4; l++) {
        int idx = tid + l * 256;
        int nr = idx >> 4, kc = idx & 15;
        size_t orow = (size_t)(n0 + nr) * DD + k0 + kc * 4;
        #pragma unroll
        for (int j = 0; j < 4; j++)
            g_wo[orow + j] = __float2half_rn(ts[kc * 4 + j][nr]);
    }
}

// ---------------------------------------------------------------------------
// Pipelined GEMM: M128 x N128 CTA, K chunks of 32, 2 stages, 2 tiles/stage
// (A | B), single-pass fp16. Warp tile 64x32 (2M x 4N). 2 CTAs/SM.
// ---------------------------------------------------------------------------
#define CROWB 80
#define CTILE (128 * CROWB)       // 10240
#define CSTAGE (2 * CTILE)        // 20480
#define GSM_BYTES (2 * CSTAGE)    // 40960

__device__ __forceinline__ void load_stage_g(
    uint32_t sm, const __half* __restrict__ A, const __half* __restrict__ B,
    int k0, int tid)
{
    #pragma unroll
    for (int l = 0; l < 2; l++) {
        int idx = tid + l * 256;
        int r = idx >> 2, c = idx & 3;
        uint32_t dof = (uint32_t)(r * CROWB + c * 16);
        size_t   sof = ((size_t)r * DD + k0) * 2 + c * 16;
        cpasync16(sm + 0 * CTILE + dof, (const char*)A + sof);
        cpasync16(sm + 1 * CTILE + dof, (const char*)B + sof);
    }
}

__device__ __forceinline__ void gemm_body(
    uint32_t smem_base, uint32_t a_lane, uint32_t b_lane,
    const __half* A, const __half* B, int tid, float acc[4][4][4])
{
    load_stage_g(smem_base,          A, B, 0,  tid);
    CP_COMMIT();
    load_stage_g(smem_base + CSTAGE, A, B, 32, tid);
    CP_COMMIT();

    for (int ch = 0; ch < 32; ch++) {
        if (ch >= 30) { CP_WAIT0(); } else { CP_WAIT1(); }
        __syncthreads();
        const uint32_t st = smem_base + (uint32_t)(ch & 1) * CSTAGE;

        #pragma unroll
        for (int ks = 0; ks < 2; ks++) {
            const uint32_t koff = ks * 32;
            uint32_t a[4][4];
            #pragma unroll
            for (int am = 0; am < 4; am++)
                ldsm_x4(st + 0 * CTILE + a_lane + am * 16 * CROWB + koff, a[am]);
            uint32_t b[2][4];
            #pragma unroll
            for (int bn = 0; bn < 2; bn++)
                ldsm_x4(st + 1 * CTILE + b_lane + bn * 16 * CROWB + koff, b[bn]);

            #pragma unroll
            for (int am = 0; am < 4; am++)
                #pragma unroll
                for (int bn = 0; bn < 2; bn++) {
                    mma_f16(acc[am][2*bn],   a[am], b[bn][0], b[bn][2]);
                    mma_f16(acc[am][2*bn+1], a[am], b[bn][1], b[bn][3]);
                }
        }
        __syncthreads();
        if (ch + 2 < 32) {
            load_stage_g(smem_base + (uint32_t)(ch & 1) * CSTAGE,
                         A, B, (ch + 2) * 32, tid);
            CP_COMMIT();
        }
    }
}

// ---------------------------------------------------------------------------
// QKV GEMM: Q -> hi/lo fp16 (unscaled); K, V -> single fp16. 2 CTAs/SM.
// ---------------------------------------------------------------------------
__global__ __launch_bounds__(256, 2) void qkv_mma_kernel(
    const float* __restrict__ bq, const float* __restrict__ bk,
    const float* __restrict__ bv)
{
    extern __shared__ char smem[];
    const uint32_t smem_base = smem_to_u32(smem);
    const int tid  = threadIdx.x;
    const int lane = tid & 31;
    const int wid  = tid >> 5;
    const int warpM = wid & 1;          // 2 groups x 64 rows
    const int warpN = wid >> 1;         // 4 groups x 32 cols

    const int m0   = blockIdx.x * 128;
    const int hg   = blockIdx.y;
    const int proj = blockIdx.z;

    const float* bias = (proj == 0) ? bq : (proj == 1) ? bk : bv;
    __half* ohi = (proj == 0) ? g_qhi : (proj == 1) ? g_k : g_v;

    const size_t brow = ((size_t)proj * HH * DKH + (size_t)hg * 128) * DD;

    float acc[4][4][4] = {};

    const int lrow  = lane & 15;
    const int lhalf = lane >> 4;
    const uint32_t a_lane = (uint32_t)((warpM * 64 + lrow) * CROWB + lhalf * 16);
    const uint32_t b_lane = (uint32_t)((warpN * 32 + lrow) * CROWB + lhalf * 16);

    gemm_body(smem_base, a_lane, b_lane,
              g_x + (size_t)m0 * DD, g_w + brow, tid, acc);

    #pragma unroll
    for (int am = 0; am < 4; am++) {
        #pragma unroll
        for (int rh = 0; rh < 2; rh++) {
            const int token = m0 + warpM * 64 + am * 16 + rh * 8 + (lane >> 2);
            const int b_ = token >> 11;
            const int s_ = token & (SS - 1);
            #pragma unroll
            for (int na = 0; na < 4; na++) {
                const int ng = hg * 128 + warpN * 32 + na * 8 + (lane & 3) * 2;
                const int h  = ng >> 6;
                const int dk = ng & 63;
                float v0 = acc[am][na][rh*2+0] + __ldg(&bias[h*DKH + dk]);
                float v1 = acc[am][na][rh*2+1] + __ldg(&bias[h*DKH + dk+1]);
                __half h0, h1; float l0, l1;
                split2h(v0, h0, l0); split2h(v1, h1, l1);
                size_t idx = ((size_t)(b_ * HH + h) * SS + s_) * DKH + dk;
                *(__half2*)&ohi[idx] = __half2(h0, h1);
                if (proj == 0)
                    *(__half2*)&g_qlo[idx] =
                        __half2(__float2half_rn(l0), __float2half_rn(l1));
            }
        }
    }
}

// ---------------------------------------------------------------------------
// Output projection: out = ctx @ Wo + bo (fp32 out). Single-pass. 2 CTAs/SM.
// ---------------------------------------------------------------------------
__global__ __launch_bounds__(256, 2) void out_mma_kernel(
    const float* __restrict__ bo, float* __restrict__ out)
{
    extern __shared__ char smem[];
    const uint32_t smem_base = smem_to_u32(smem);
    const int tid  = threadIdx.x;
    const int lane = tid & 31;
    const int wid  = tid >> 5;
    const int warpM = wid & 1;
    const int warpN = wid >> 1;

    const int m0 = blockIdx.x * 128;
    const int n0 = blockIdx.y * 128;

    float acc[4][4][4] = {};

    const int lrow  = lane & 15;
    const int lhalf = lane >> 4;
    const uint32_t a_lane = (uint32_t)((warpM * 64 + lrow) * CROWB + lhalf * 16);
    const uint32_t b_lane = (uint32_t)((warpN * 32 + lrow) * CROWB + lhalf * 16);

    gemm_body(smem_base, a_lane, b_lane,
              g_c + (size_t)m0 * DD, g_wo + (size_t)n0 * DD, tid, acc);

    #pragma unroll
    for (int am = 0; am < 4; am++) {
        #pragma unroll
        for (int rh = 0; rh < 2; rh++) {
            const int token = m0 + warpM * 64 + am * 16 + rh * 8 + (lane >> 2);
            #pragma unroll
            for (int na = 0; na < 4; na++) {
                const int n = n0 + warpN * 32 + na * 8 + (lane & 3) * 2;
                float2 o;
                o.x = acc[am][na][rh*2+0] + __ldg(&bo[n]);
                o.y = acc[am][na][rh*2+1] + __ldg(&bo[n+1]);
                *(float2*)&out[(size_t)token * DD + n] = o;
            }
        }
    }
}

// ---------------------------------------------------------------------------
// Flash attention: 32 q-rows/warp (q-tile 256), grid (8, 32), block 256.
// S = 2-pass (Q hi/lo x K single); PV = single-pass (P fp16 x V single).
// Scores scaled by 0.125 in fp32 after MMA.
// ---------------------------------------------------------------------------
#define AROWB 144                    // 72 fp16 per row
#define ATILE (64 * AROWB)           // 9216
#define AST (2 * ATILE)              // 18432 : K | V
#define ATTN_SM_BYTES (2 * AST)      // 36864

__device__ __forceinline__ void attn_load_stage(
    uint32_t sm, size_t key0, int tid)
{
    #pragma unroll
    for (int l = 0; l < 2; l++) {
        int idx = tid + l * 256;
        int r = idx >> 3, c = idx & 7;
        uint32_t dof = (uint32_t)(r * AROWB + c * 16);
        size_t   sof = ((size_t)r * DKH) * 2 + c * 16;
        cpasync16(sm + 0 * ATILE + dof, (const char*)(g_k + key0) + sof);
        cpasync16(sm + 1 * ATILE + dof, (const char*)(g_v + key0) + sof);
    }
}

__global__ __launch_bounds__(256, 1) void attn_mma_kernel()
{
    extern __shared__ char smem[];
    const uint32_t smem_base = smem_to_u32(smem);
    const int tid  = threadIdx.x;
    const int lane = tid & 31;
    const int w    = tid >> 5;          // warp 0..7 -> q rows w*32..w*32+31

    const int bh = blockIdx.y;
    const int q0 = blockIdx.x * 256;
    const size_t base = (size_t)bh * SS * DKH;

    const int lrow  = lane & 15;
    const int lhalf = lane >> 4;

    // ---- stage Q in two phases (hi then lo) through the whole smem ----
    uint32_t qhi[2][4][4], qlo[2][4][4];   // [am][ks][regs]
    #pragma unroll
    for (int phase = 0; phase < 2; phase++) {
        const __half* Qp = (phase == 0 ? g_qhi : g_qlo) + base + (size_t)q0 * DKH;
        #pragma unroll
        for (int l = 0; l < 8; l++) {
            int idx = tid + l * 256;
            int r = idx >> 3, c = idx & 7;
            cpasync16(smem_base + (uint32_t)(r * AROWB + c * 16),
                      (const char*)Qp + ((size_t)r * DKH) * 2 + c * 16);
        }
        CP_COMMIT();
        CP_WAIT0();
        __syncthreads();
        #pragma unroll
        for (int am = 0; am < 2; am++) {
            const uint32_t qa = smem_base +
                (uint32_t)((w * 32 + am * 16 + lrow) * AROWB + lhalf * 16);
            #pragma unroll
            for (int ks = 0; ks < 4; ks++) {
                if (phase == 0) ldsm_x4(qa + ks * 32, qhi[am][ks]);
                else            ldsm_x4(qa + ks * 32, qlo[am][ks]);
            }
        }
        __syncthreads();
    }

    attn_load_stage(smem_base, base, tid);
    CP_COMMIT();
    attn_load_stage(smem_base + AST, base + (size_t)64 * DKH, tid);
    CP_COMMIT();

    float o[2][8][4] = {};
    float m[2][2], l[2][2];
    #pragma unroll
    for (int am = 0; am < 2; am++) {
        m[am][0] = -1e30f; m[am][1] = -1e30f;
        l[am][0] = 0.0f;   l[am][1] = 0.0f;
    }

    const uint32_t lane_off = (uint32_t)(lrow * AROWB + lhalf * 16);

    for (int ch = 0; ch < 32; ch++) {
        if (ch >= 30) { CP_WAIT0(); } else { CP_WAIT1(); }
        __syncthreads();
        const uint32_t st = smem_base + (uint32_t)(ch & 1) * AST;
        const uint32_t kb = st + lane_off;

        // ---- S = Q K^T : 32 x 64 per warp, 2-pass (Q hi/lo) ----
        float s[2][8][4] = {};
        #pragma unroll
        for (int ks = 0; ks < 4; ks++) {
            const uint32_t koff = ks * 32;
            uint32_t kh[4][4];
            #pragma unroll
            for (int bn = 0; bn < 4; bn++)
                ldsm_x4(kb + bn * 16 * AROWB + koff, kh[bn]);
            // pass 1: qhi x k (16 independent MMAs)
            #pragma unroll
            for (int bn = 0; bn < 4; bn++)
                #pragma unroll
                for (int am = 0; am < 2; am++) {
                    mma_f16(s[am][2*bn],   qhi[am][ks], kh[bn][0], kh[bn][2]);
                    mma_f16(s[am][2*bn+1], qhi[am][ks], kh[bn][1], kh[bn][3]);
                }
            // pass 2: qlo x k
            #pragma unroll
            for (int bn = 0; bn < 4; bn++)
                #pragma unroll
                for (int am = 0; am < 2; am++) {
                    mma_f16(s[am][2*bn],   qlo[am][ks], kh[bn][0], kh[bn][2]);
                    mma_f16(s[am][2*bn+1], qlo[am][ks], kh[bn][1], kh[bn][3]);
                }
        }
        // fold the 1/sqrt(dk) scale in fp32
        #pragma unroll
        for (int am = 0; am < 2; am++)
            #pragma unroll
            for (int j = 0; j < 8; j++)
                #pragma unroll
                for (int c = 0; c < 4; c++)
                    s[am][j][c] *= 0.125f;

        // ---- online softmax per am group ----
        #pragma unroll
        for (int am = 0; am < 2; am++) {
            float mxA = -1e30f, mxB = -1e30f;
            #pragma unroll
            for (int j = 0; j < 8; j++) {
                mxA = fmaxf(mxA, fmaxf(s[am][j][0], s[am][j][1]));
                mxB = fmaxf(mxB, fmaxf(s[am][j][2], s[am][j][3]));
            }
            #pragma unroll
            for (int msk = 1; msk < 4; msk <<= 1) {
                mxA = fmaxf(mxA, __shfl_xor_sync(0xffffffffu, mxA, msk));
                mxB = fmaxf(mxB, __shfl_xor_sync(0xffffffffu, mxB, msk));
            }
            const float mnA = fmaxf(m[am][0], mxA);
            const float mnB = fmaxf(m[am][1], mxB);
            const float fA = __expf(m[am][0] - mnA);
            const float fB = __expf(m[am][1] - mnB);
            m[am][0] = mnA; m[am][1] = mnB;
            float rsA = 0.0f, rsB = 0.0f;
            #pragma unroll
            for (int j = 0; j < 8; j++) {
                s[am][j][0] = __expf(s[am][j][0] - mnA); rsA += s[am][j][0];
                s[am][j][1] = __expf(s[am][j][1] - mnA); rsA += s[am][j][1];
                s[am][j][2] = __expf(s[am][j][2] - mnB); rsB += s[am][j][2];
                s[am][j][3] = __expf(s[am][j][3] - mnB); rsB += s[am][j][3];
            }
            #pragma unroll
            for (int msk = 1; msk < 4; msk <<= 1) {
                rsA += __shfl_xor_sync(0xffffffffu, rsA, msk);
                rsB += __shfl_xor_sync(0xffffffffu, rsB, msk);
            }
            l[am][0] = l[am][0] * fA + rsA;
            l[am][1] = l[am][1] * fB + rsB;
            #pragma unroll
            for (int j = 0; j < 8; j++) {
                o[am][j][0] *= fA; o[am][j][1] *= fA;
                o[am][j][2] *= fB; o[am][j][3] *= fB;
            }
        }

        // ---- O += P V : single-pass (P rounded to fp16) ----
        #pragma unroll
        for (int j = 0; j < 4; j++) {
            uint32_t ph[2][4];
            #pragma unroll
            for (int am = 0; am < 2; am++) {
                ph[am][0] = pkh(s[am][2*j][0],   s[am][2*j][1]);
                ph[am][1] = pkh(s[am][2*j][2],   s[am][2*j][3]);
                ph[am][2] = pkh(s[am][2*j+1][0], s[am][2*j+1][1]);
                ph[am][3] = pkh(s[am][2*j+1][2], s[am][2*j+1][3]);
            }
            const uint32_t vrow = st + 1 * ATILE +
                (uint32_t)((j * 16 + lrow) * AROWB + lhalf * 16);
            uint32_t vh[4][4];
            #pragma unroll
            for (int dvp = 0; dvp < 4; dvp++)
                ldsm_x4_t(vrow + dvp * 32, vh[dvp]);
            #pragma unroll
            for (int dvp = 0; dvp < 4; dvp++)
                #pragma unroll
                for (int am = 0; am < 2; am++) {
                    mma_f16(o[am][2*dvp],   ph[am], vh[dvp][0], vh[dvp][1]);
                    mma_f16(o[am][2*dvp+1], ph[am], vh[dvp][2], vh[dvp][3]);
                }
        }
        __syncthreads();
        if (ch + 2 < 32) {
            attn_load_stage(smem_base + (uint32_t)(ch & 1) * AST,
                            base + (size_t)((ch + 2) * 64) * DKH, tid);
            CP_COMMIT();
        }
    }

    // ---- epilogue: normalize, write ctx single fp16 [token][1024] ----
    const int b_ = bh / HH;
    const int h_ = bh % HH;
    #pragma unroll
    for (int am = 0; am < 2; am++) {
        const float invA = 1.0f / l[am][0];
        const float invB = 1.0f / l[am][1];
        const int rA = q0 + w * 32 + am * 16 + (lane >> 2);
        const int tokenA = b_ * SS + rA;
        const int tokenB = tokenA + 8;
        #pragma unroll
        for (int jj = 0; jj < 8; jj++) {
            const int col = h_ * DKH + jj * 8 + (lane & 3) * 2;
            {
                union { __half2 b2; uint32_t u; } t;
                t.u = pkh(o[am][jj][0] * invA, o[am][jj][1] * invA);
                *(__half2*)&g_c[(size_t)tokenA * DD + col] = t.b2;
            }
            {
                union { __half2 b2; uint32_t u; } t;
                t.u = pkh(o[am][jj][2] * invB, o[am][jj][3] * invB);
                *(__half2*)&g_c[(size_t)tokenB * DD + col] = t.b2;
            }
        }
    }
}

// ---------------------------------------------------------------------------
extern "C" void kernel_launch(void* const* d_in, const int* in_sizes, int n_in,
                              void* d_out, int out_size)
{
    const float* X  = (const float*)d_in[0];
    const float* Wq = (const float*)d_in[1];
    const float* bq = (const float*)d_in[2];
    const float* Wk = (const float*)d_in[3];
    const float* bk = (const float*)d_in[4];
    const float* Wv = (const float*)d_in[5];
    const float* bv = (const float*)d_in[6];
    const float* Wo = (const float*)d_in[7];
    const float* bo = (const float*)d_in[8];
    float* out = (float*)d_out;

    cudaFuncSetAttribute(qkv_mma_kernel,
                         cudaFuncAttributeMaxDynamicSharedMemorySize, GSM_BYTES);
    cudaFuncSetAttribute(out_mma_kernel,
                         cudaFuncAttributeMaxDynamicSharedMemorySize, GSM_BYTES);
    cudaFuncSetAttribute(attn_mma_kernel,
                         cudaFuncAttributeMaxDynamicSharedMemorySize, ATTN_SM_BYTES);

    conv_x_kernel<<<2048, 256>>>((const float4*)X);
    conv_w_kernel<<<dim3(16, 16, 3), 256>>>(Wq, Wk, Wv);
    conv_wo_kernel<<<dim3(16, 16), 256>>>(Wo);
    qkv_mma_kernel<<<dim3(32, 8, 3), 256, GSM_BYTES>>>(bq, bk, bv);
    attn_mma_kernel<<<dim3(8, 32), 256, ATTN_SM_BYTES>>>();
    out_mma_kernel<<<dim3(32, 8), 256, GSM_BYTES>>>(bo, out);
}